// round 4
// baseline (speedup 1.0000x reference)
#include <cuda_runtime.h>
#include <cstdint>
#include <cstddef>

// Problem dims
#define T_STEPS 512
#define BATCH   256
#define NF      160
#define H       128
#define GC      512   // 4*H gate columns

// Recurrent org: 32 clusters (teams) x 4 CTAs x 512 threads.
// Team owns 8 batch rows; CTA owns 32 hidden units (=128 gate cols) of BOTH layers.
// Thread owns ONE gate column (all 8 rows) over a K-quarter.
#define TEAMS 32
#define ROWS_PER_TEAM 8
#define UNITS_PER_CTA 32
#define HP 128   // h-buffer row stride (broadcast loads: no pad needed)

// -------- global scratch (static __device__, allocation-free) --------
__device__ float g_xpre[(size_t)T_STEPS * BATCH * GC];       // 256 MB

// ---------------- f32x2 helpers ----------------
__device__ __forceinline__ void ffma2(unsigned long long& d,
                                      unsigned long long a,
                                      unsigned long long b) {
    asm("fma.rn.f32x2 %0, %1, %2, %0;" : "+l"(d) : "l"(a), "l"(b));
}
__device__ __forceinline__ float hsum2(unsigned long long v) {
    unsigned lo, hi;
    asm("mov.b64 {%0,%1}, %2;" : "=r"(lo), "=r"(hi) : "l"(v));
    return __uint_as_float(lo) + __uint_as_float(hi);
}

// ---------------- cluster helpers ----------------
__device__ __forceinline__ void cluster_sync_() {
    asm volatile("barrier.cluster.arrive.aligned;" ::: "memory");
    asm volatile("barrier.cluster.wait.aligned;" ::: "memory");
}
__device__ __forceinline__ unsigned ctarank_() {
    unsigned r;
    asm("mov.u32 %0, %%cluster_ctarank;" : "=r"(r));
    return r;
}
__device__ __forceinline__ void st_peer_f32(uint32_t local_smem_addr, int rank, float v) {
    uint32_t ra;
    asm("mapa.shared::cluster.u32 %0, %1, %2;" : "=r"(ra) : "r"(local_smem_addr), "r"(rank));
    asm volatile("st.shared::cluster.f32 [%0], %1;" :: "r"(ra), "f"(v) : "memory");
}

// Swizzled weight addressing: row(col) = 128 floats = 32 chunks of 16B.
// word offset of (col, k): col*128 + ((k>>2) ^ (col&7))*4   -> conflict-free
__device__ __forceinline__ int wswz(int col, int k) {
    return col * 128 + (((k >> 2) ^ (col & 7)) << 2);
}

// ---------------------------------------------------------------
// Precompute: Xpre[t][b][gc] = x[b][t][:] @ Wih0[gc][:] + bih0[gc]+bhh0[gc]
#define PRE_SMEM (2 * 64 * 164 * 4)
__global__ __launch_bounds__(256) void precompute_kernel(
    const float* __restrict__ x,
    const float* __restrict__ Wih0,
    const float* __restrict__ bih0,
    const float* __restrict__ bhh0)
{
    extern __shared__ float sm[];
    float* xs = sm;              // [64][164]
    float* ws = sm + 64 * 164;   // [64][164]

    const int t   = blockIdx.x;
    const int b0  = blockIdx.y * 64;
    const int gc0 = blockIdx.z * 64;
    const int tid = threadIdx.x;

    for (int idx = tid; idx < 64 * 40; idx += 256) {
        int row = idx / 40;
        int q   = (idx % 40) * 4;
        *(float4*)&xs[row * 164 + q] =
            *(const float4*)&x[((size_t)(b0 + row) * T_STEPS + t) * NF + q];
        *(float4*)&ws[row * 164 + q] =
            *(const float4*)&Wih0[(size_t)(gc0 + row) * NF + q];
    }
    __syncthreads();

    const int tx = tid & 15;
    const int ty = tid >> 4;

    unsigned long long acc[4][4];
#pragma unroll
    for (int i = 0; i < 4; i++)
#pragma unroll
        for (int j = 0; j < 4; j++) acc[i][j] = 0ull;

#pragma unroll 4
    for (int k = 0; k < NF; k += 4) {
        ulonglong2 av[4], bv[4];
#pragma unroll
        for (int i = 0; i < 4; i++) av[i] = *(const ulonglong2*)&xs[(ty + 16 * i) * 164 + k];
#pragma unroll
        for (int j = 0; j < 4; j++) bv[j] = *(const ulonglong2*)&ws[(tx + 16 * j) * 164 + k];
#pragma unroll
        for (int i = 0; i < 4; i++)
#pragma unroll
            for (int j = 0; j < 4; j++) {
                ffma2(acc[i][j], av[i].x, bv[j].x);
                ffma2(acc[i][j], av[i].y, bv[j].y);
            }
    }

#pragma unroll
    for (int i = 0; i < 4; i++) {
        int b = b0 + ty + 16 * i;
#pragma unroll
        for (int j = 0; j < 4; j++) {
            int gc = gc0 + tx + 16 * j;
            float bias = __ldg(&bih0[gc]) + __ldg(&bhh0[gc]);
            g_xpre[((size_t)t * BATCH + b) * GC + gc] = hsum2(acc[i][j]) + bias;
        }
    }
}

// ---------------------------------------------------------------
__device__ __forceinline__ float sigm(float v)  { return 1.0f / (1.0f + __expf(-v)); }
__device__ __forceinline__ float tanhx(float v) { return 1.0f - 2.0f / (__expf(2.0f * v) + 1.0f); }

// Accumulate 8 rows of one gate-column jc over k in [kbase, kbase+klen).
__device__ __forceinline__ void col_acc(
    const float* __restrict__ W, const float* __restrict__ Hm,
    int jc, int kbase, int klen, unsigned long long acc[8])
{
#pragma unroll 8
    for (int k = kbase; k < kbase + klen; k += 4) {
        ulonglong2 wv = *(const ulonglong2*)&W[wswz(jc, k)];
#pragma unroll
        for (int i = 0; i < 8; i++) {
            ulonglong2 hv = *(const ulonglong2*)&Hm[i * HP + k];
            ffma2(acc[i], wv.x, hv.x);
            ffma2(acc[i], wv.y, hv.y);
        }
    }
}

// smem: 3 weight slices (swizzled, 64KB each) + 2x2 h buffers + 4-group gate
// staging + layer-1 bias
#define REC_SMEM ((3 * 128 * 128 + 2 * 2 * 8 * HP + 4 * 8 * 128 + 128) * 4)

__global__ __launch_bounds__(512, 1) __cluster_dims__(4, 1, 1)
void lstm_recurrent_kernel(
    const float* __restrict__ h0,
    const float* __restrict__ c0,
    const float* __restrict__ Whh0,
    const float* __restrict__ Wih1,
    const float* __restrict__ Whh1,
    const float* __restrict__ bih1,
    const float* __restrict__ bhh1,
    float* __restrict__ out)
{
    extern __shared__ float sm[];
    float* w0  = sm;                   // [128 cols][128] swizzled W_hh0 slice
    float* w1i = w0  + 128 * 128;      // W_ih1 slice
    float* w1h = w1i + 128 * 128;      // W_hh1 slice
    float* h1b = w1h + 128 * 128;      // [2][8][HP]
    float* h2b = h1b + 2 * 8 * HP;     // [2][8][HP]
    float* gs  = h2b + 2 * 8 * HP;     // [4 kgroups][8][128]
    float* b1s = gs  + 4 * 8 * 128;    // [128]

    const int tid   = threadIdx.x;
    const int team  = blockIdx.x >> 2;
    const int rank  = (int)ctarank_();
    const int brow0 = team * ROWS_PER_TEAM;
    const int ubase = rank * UNITS_PER_CTA;

    // --- load weight slices into swizzled smem (col j = gate*32 + unit) ---
    for (int idx = tid; idx < 128 * 32; idx += 512) {
        int j = idx >> 5;           // local col
        int q = idx & 31;           // 16B chunk
        int grow = (j >> 5) * H + ubase + (j & 31);
        int dst = j * 128 + ((q ^ (j & 7)) << 2);
        *(float4*)&w0 [dst] = *(const float4*)&Whh0[(size_t)grow * H + q * 4];
        *(float4*)&w1i[dst] = *(const float4*)&Wih1[(size_t)grow * H + q * 4];
        *(float4*)&w1h[dst] = *(const float4*)&Whh1[(size_t)grow * H + q * 4];
    }
    for (int j = tid; j < 128; j += 512) {
        int grow = (j >> 5) * H + ubase + (j & 31);
        b1s[j] = bih1[grow] + bhh1[grow];
    }
    for (int idx = tid; idx < 8 * 32; idx += 512) {
        int r = idx >> 5;
        int q = (idx & 31) * 4;
        *(float4*)&h1b[r * HP + q] = *(const float4*)&h0[((size_t)(brow0 + r)) * H + q];
        *(float4*)&h2b[r * HP + q] = *(const float4*)&h0[((size_t)(BATCH + brow0 + r)) * H + q];
    }
    __syncthreads();

    // pointwise thread mapping (tid < 256)
    const int pr = (tid >> 5) & 7;
    const int pu = tid & 31;
    float c1 = 0.f, c2 = 0.f, bb0 = 0.f, bb1 = 0.f, bb2 = 0.f, bb3 = 0.f;
    if (tid < 256) {
        c1 = c0[((size_t)(brow0 + pr)) * H + ubase + pu];
        c2 = c0[((size_t)(BATCH + brow0 + pr)) * H + ubase + pu];
        bb0 = b1s[      pu];
        bb1 = b1s[ 32 + pu];
        bb2 = b1s[ 64 + pu];
        bb3 = b1s[ 96 + pu];
    }
    cluster_sync_();

    // GEMM mapping: col jc = tid&127, K-group g = tid>>7.
    const int jc = tid & 127;
    const int g  = tid >> 7;

    const uint32_t h1a0 = (uint32_t)__cvta_generic_to_shared(&h1b[pr * HP + ubase + pu]);
    const uint32_t h1a1 = (uint32_t)__cvta_generic_to_shared(&h1b[8 * HP + pr * HP + ubase + pu]);
    const uint32_t h2a0 = (uint32_t)__cvta_generic_to_shared(&h2b[pr * HP + ubase + pu]);
    const uint32_t h2a1 = (uint32_t)__cvta_generic_to_shared(&h2b[8 * HP + pr * HP + ubase + pu]);

    // phase-B operand selection per thread (constant across steps)
    const float* wB = (g < 2) ? w1i : w1h;
    const int kbB = (g & 1) * 64;

    for (int t = 0; t < T_STEPS; t++) {
        const int p = t & 1;
        float* h1cur = h1b + p * 8 * HP;
        float* h1nxt = h1b + (p ^ 1) * 8 * HP;
        float* h2cur = h2b + p * 8 * HP;

        // prefetch xpre gates for the pointwise threads (hidden behind gemmA)
        float xg0 = 0.f, xg1 = 0.f, xg2 = 0.f, xg3 = 0.f;
        if (tid < 256) {
            const float* xp = &g_xpre[((size_t)t * BATCH + brow0 + pr) * GC + ubase + pu];
            xg0 = __ldg(&xp[0 * H]);
            xg1 = __ldg(&xp[1 * H]);
            xg2 = __ldg(&xp[2 * H]);
            xg3 = __ldg(&xp[3 * H]);
        }

        // ================= Phase A: layer-0 recurrent (K=128, 4x32 split) ===
        {
            unsigned long long acc[8] = {0,0,0,0,0,0,0,0};
            col_acc(w0, h1cur, jc, g * 32, 32, acc);
#pragma unroll
            for (int i = 0; i < 8; i++)
                gs[(g * 8 + i) * 128 + jc] = hsum2(acc[i]);
        }
        __syncthreads();

        if (tid < 256) {
            float gi = xg0, gf = xg1, gg = xg2, go = xg3;
#pragma unroll
            for (int q = 0; q < 4; q++) {
                const float* gq = &gs[q * 1024 + pr * 128];
                gi += gq[      pu];
                gf += gq[ 32 + pu];
                gg += gq[ 64 + pu];
                go += gq[ 96 + pu];
            }
            float iv = sigm(gi), fv = sigm(gf), gv = tanhx(gg), ov = sigm(go);
            c1 = fv * c1 + iv * gv;
            float h1v = ov * tanhx(c1);
            uint32_t a = p ? h1a0 : h1a1;   // write NEXT h1 buffer in all CTAs
#pragma unroll
            for (int rk = 0; rk < 4; rk++) st_peer_f32(a, rk, h1v);
        }
        // Single cluster sync per step: publishes h1_t now; publishes h2_t for
        // step t+1 via the next iteration's sync. Double buffers cover the rest.
        cluster_sync_();

        // ================= Phase B: layer-1 (K=256 over [W_ih1|W_hh1]) ======
        {
            const float* hB = (g < 2) ? h1nxt : h2cur;
            unsigned long long acc[8] = {0,0,0,0,0,0,0,0};
            col_acc(wB, hB, jc, kbB, 64, acc);
            __syncthreads();   // phase-A gs reads complete before overwrite
#pragma unroll
            for (int i = 0; i < 8; i++)
                gs[(g * 8 + i) * 128 + jc] = hsum2(acc[i]);
        }
        __syncthreads();

        if (tid < 256) {
            float gi = bb0, gf = bb1, gg = bb2, go = bb3;
#pragma unroll
            for (int q = 0; q < 4; q++) {
                const float* gq = &gs[q * 1024 + pr * 128];
                gi += gq[      pu];
                gf += gq[ 32 + pu];
                gg += gq[ 64 + pu];
                go += gq[ 96 + pu];
            }
            float iv = sigm(gi), fv = sigm(gf), gv = tanhx(gg), ov = sigm(go);
            c2 = fv * c2 + iv * gv;
            float h2v = ov * tanhx(c2);
            uint32_t a = p ? h2a0 : h2a1;   // write NEXT h2 buffer in all CTAs
#pragma unroll
            for (int rk = 0; rk < 4; rk++) st_peer_f32(a, rk, h2v);
            if (t == T_STEPS - 1)
                out[(size_t)(brow0 + pr) * H + ubase + pu] = h2v;
        }
        __syncthreads();   // gs settled before next phase-A overwrite
    }
    cluster_sync_();   // drain in-flight peer stores before exit
}

// ---------------------------------------------------------------
extern "C" void kernel_launch(void* const* d_in, const int* in_sizes, int n_in,
                              void* d_out, int out_size)
{
    const float* x    = (const float*)d_in[0];
    const float* h0   = (const float*)d_in[1];
    const float* c0   = (const float*)d_in[2];
    const float* Wih0 = (const float*)d_in[3];
    const float* Whh0 = (const float*)d_in[4];
    const float* bih0 = (const float*)d_in[5];
    const float* bhh0 = (const float*)d_in[6];
    const float* Wih1 = (const float*)d_in[7];
    const float* Whh1 = (const float*)d_in[8];
    const float* bih1 = (const float*)d_in[9];
    const float* bhh1 = (const float*)d_in[10];
    float* out = (float*)d_out;

    cudaFuncSetAttribute(precompute_kernel,
                         cudaFuncAttributeMaxDynamicSharedMemorySize, PRE_SMEM);
    cudaFuncSetAttribute(lstm_recurrent_kernel,
                         cudaFuncAttributeMaxDynamicSharedMemorySize, REC_SMEM);

    dim3 pgrid(T_STEPS, 4, 8);
    precompute_kernel<<<pgrid, 256, PRE_SMEM>>>(x, Wih0, bih0, bhh0);

    lstm_recurrent_kernel<<<TEAMS * 4, 512, REC_SMEM>>>(
        h0, c0, Whh0, Wih1, Whh1, bih1, bhh1, out);
}

// round 5
// speedup vs baseline: 1.4259x; 1.4259x over previous
#include <cuda_runtime.h>
#include <cstdint>
#include <cstddef>

// Problem dims
#define T_STEPS 512
#define BATCH   256
#define NF      160
#define H       128
#define GC      512   // 4*H gate columns

// Recurrent org: 32 clusters x 4 CTAs x 512 threads.
// Team owns 8 batch rows; CTA owns 32 hidden units (=128 gate cols) of BOTH layers.
// Merged-GEMM iteration: one burst computes gemmA(t+1) and gemmB(t) together.
#define TEAMS 32
#define ROWS_PER_TEAM 8
#define UNITS_PER_CTA 32
#define HB 1024   // floats per h buffer (8 rows x 128)

// -------- global scratch (static __device__, allocation-free) --------
__device__ float g_xpre[(size_t)T_STEPS * BATCH * GC];       // 256 MB

// ---------------- f32x2 helpers ----------------
__device__ __forceinline__ void ffma2(unsigned long long& d,
                                      unsigned long long a,
                                      unsigned long long b) {
    asm("fma.rn.f32x2 %0, %1, %2, %0;" : "+l"(d) : "l"(a), "l"(b));
}
__device__ __forceinline__ float hsum2(unsigned long long v) {
    unsigned lo, hi;
    asm("mov.b64 {%0,%1}, %2;" : "=r"(lo), "=r"(hi) : "l"(v));
    return __uint_as_float(lo) + __uint_as_float(hi);
}

// ---------------- cluster helpers ----------------
__device__ __forceinline__ void cluster_sync_() {
    asm volatile("barrier.cluster.arrive.aligned;" ::: "memory");
    asm volatile("barrier.cluster.wait.aligned;" ::: "memory");
}
__device__ __forceinline__ unsigned ctarank_() {
    unsigned r;
    asm("mov.u32 %0, %%cluster_ctarank;" : "=r"(r));
    return r;
}
__device__ __forceinline__ void st_peer_f32(uint32_t local_smem_addr, int rank, float v) {
    uint32_t ra;
    asm("mapa.shared::cluster.u32 %0, %1, %2;" : "=r"(ra) : "r"(local_smem_addr), "r"(rank));
    asm volatile("st.shared::cluster.f32 [%0], %1;" :: "r"(ra), "f"(v) : "memory");
}

// Swizzled weight layout: col row = 128 floats = 32 chunks of 16B.
// word offset of (col,k):  col*128 + ((k>>2)^(col&7))*4  -> conflict-free
__device__ __forceinline__ int wswz(int col, int k) {
    return col * 128 + (((k >> 2) ^ (col & 7)) << 2);
}

// ---------------------------------------------------------------
// Precompute kernel (unchanged, known-good)
#define PRE_SMEM (2 * 64 * 164 * 4)
__global__ __launch_bounds__(256) void precompute_kernel(
    const float* __restrict__ x,
    const float* __restrict__ Wih0,
    const float* __restrict__ bih0,
    const float* __restrict__ bhh0)
{
    extern __shared__ float sm[];
    float* xs = sm;              // [64][164]
    float* ws = sm + 64 * 164;   // [64][164]

    const int t   = blockIdx.x;
    const int b0  = blockIdx.y * 64;
    const int gc0 = blockIdx.z * 64;
    const int tid = threadIdx.x;

    for (int idx = tid; idx < 64 * 40; idx += 256) {
        int row = idx / 40;
        int q   = (idx % 40) * 4;
        *(float4*)&xs[row * 164 + q] =
            *(const float4*)&x[((size_t)(b0 + row) * T_STEPS + t) * NF + q];
        *(float4*)&ws[row * 164 + q] =
            *(const float4*)&Wih0[(size_t)(gc0 + row) * NF + q];
    }
    __syncthreads();

    const int tx = tid & 15;
    const int ty = tid >> 4;

    unsigned long long acc[4][4];
#pragma unroll
    for (int i = 0; i < 4; i++)
#pragma unroll
        for (int j = 0; j < 4; j++) acc[i][j] = 0ull;

#pragma unroll 4
    for (int k = 0; k < NF; k += 4) {
        ulonglong2 av[4], bv[4];
#pragma unroll
        for (int i = 0; i < 4; i++) av[i] = *(const ulonglong2*)&xs[(ty + 16 * i) * 164 + k];
#pragma unroll
        for (int j = 0; j < 4; j++) bv[j] = *(const ulonglong2*)&ws[(tx + 16 * j) * 164 + k];
#pragma unroll
        for (int i = 0; i < 4; i++)
#pragma unroll
            for (int j = 0; j < 4; j++) {
                ffma2(acc[i][j], av[i].x, bv[j].x);
                ffma2(acc[i][j], av[i].y, bv[j].y);
            }
    }

#pragma unroll
    for (int i = 0; i < 4; i++) {
        int b = b0 + ty + 16 * i;
#pragma unroll
        for (int j = 0; j < 4; j++) {
            int gc = gc0 + tx + 16 * j;
            float bias = __ldg(&bih0[gc]) + __ldg(&bhh0[gc]);
            g_xpre[((size_t)t * BATCH + b) * GC + gc] = hsum2(acc[i][j]) + bias;
        }
    }
}

// ---------------------------------------------------------------
__device__ __forceinline__ float sigm(float v)  { return 1.0f / (1.0f + __expf(-v)); }
__device__ __forceinline__ float tanhx(float v) { return 1.0f - 2.0f / (__expf(2.0f * v) + 1.0f); }

// Accumulate 8 rows of col over one 32-k window of W (swizzled) x Hm.
__device__ __forceinline__ void seg_acc(
    const float* __restrict__ W, const float* __restrict__ Hm,
    int col, int kb, unsigned long long acc[8])
{
#pragma unroll
    for (int kk = 0; kk < 32; kk += 4) {
        ulonglong2 wv = *(const ulonglong2*)&W[wswz(col, kb + kk)];
#pragma unroll
        for (int r = 0; r < 8; r++) {
            ulonglong2 hv = *(const ulonglong2*)&Hm[r * 128 + kb + kk];
            ffma2(acc[r], wv.x, hv.x);
            ffma2(acc[r], wv.y, hv.y);
        }
    }
}

// smem: 3 swizzled weight slices (64KB ea) + 2x2 h buffers + gsA/gsB + bias
#define REC_SMEM ((3 * 128 * 128 + 2 * HB + 2 * HB + 8 * 128 + 8 * 128 + 128) * 4)

__global__ __launch_bounds__(512, 1) __cluster_dims__(4, 1, 1)
void lstm_recurrent_kernel(
    const float* __restrict__ h0,
    const float* __restrict__ c0,
    const float* __restrict__ Whh0,
    const float* __restrict__ Wih1,
    const float* __restrict__ Whh1,
    const float* __restrict__ bih1,
    const float* __restrict__ bhh1,
    float* __restrict__ out)
{
    extern __shared__ float sm[];
    float* w0  = sm;                   // [128 cols][128] swizzled W_hh0 slice
    float* w1i = w0  + 128 * 128;
    float* w1h = w1i + 128 * 128;
    float* h1b = w1h + 128 * 128;      // [2][8][128]
    float* h2b = h1b + 2 * HB;         // [2][8][128]
    float* gsA = h2b + 2 * HB;         // [8][128]
    float* gsB = gsA + 8 * 128;        // [8][128]
    float* b1s = gsB + 8 * 128;        // [128]

    const int tid   = threadIdx.x;
    const int team  = blockIdx.x >> 2;
    const int rank  = (int)ctarank_();
    const int brow0 = team * ROWS_PER_TEAM;
    const int ubase = rank * UNITS_PER_CTA;

    // --- load weight slices into swizzled smem (local col j = gate*32+unit) ---
    for (int idx = tid; idx < 128 * 32; idx += 512) {
        int j = idx >> 5;           // local col
        int q = idx & 31;           // 16B chunk
        int grow = (j >> 5) * H + ubase + (j & 31);
        int dst = j * 128 + ((q ^ (j & 7)) << 2);
        *(float4*)&w0 [dst] = *(const float4*)&Whh0[(size_t)grow * H + q * 4];
        *(float4*)&w1i[dst] = *(const float4*)&Wih1[(size_t)grow * H + q * 4];
        *(float4*)&w1h[dst] = *(const float4*)&Whh1[(size_t)grow * H + q * 4];
    }
    for (int j = tid; j < 128; j += 512) {
        int grow = (j >> 5) * H + ubase + (j & 31);
        b1s[j] = bih1[grow] + bhh1[grow];
    }
    // initial h states: h1[-1] -> h1b buf0; h2[-1] -> h2b buf0
    for (int idx = tid; idx < 8 * 32; idx += 512) {
        int r = idx >> 5;
        int q = (idx & 31) * 4;
        *(float4*)&h1b[r * 128 + q] = *(const float4*)&h0[((size_t)(brow0 + r)) * H + q];
        *(float4*)&h2b[r * 128 + q] = *(const float4*)&h0[((size_t)(BATCH + brow0 + r)) * H + q];
    }
    __syncthreads();

    // pointwise mapping: tid<256 -> layer-0 (c1); tid>=256 -> layer-1 (c2)
    const int pr = (tid >> 5) & 7;
    const int pu = tid & 31;
    float c1 = 0.f, c2 = 0.f, bb0 = 0.f, bb1 = 0.f, bb2 = 0.f, bb3 = 0.f;
    if (tid < 256) {
        c1 = c0[((size_t)(brow0 + pr)) * H + ubase + pu];
    } else {
        c2 = c0[((size_t)(BATCH + brow0 + pr)) * H + ubase + pu];
        bb0 = b1s[      pu];
        bb1 = b1s[ 32 + pu];
        bb2 = b1s[ 64 + pu];
        bb3 = b1s[ 96 + pu];
    }
    cluster_sync_();

    // GEMM mapping: lane = (col&7) + 8*piece; warp covers 8 cols, 4 k-pieces.
    const int lane = tid & 31;
    const int col  = ((tid >> 5) << 3) + (lane & 7);   // 0..127
    const int kb   = (lane >> 3) * 32;                 // piece base: 0/32/64/96

    // per-buffer smem addresses of this thread's pointwise h element
    const uint32_t h1a0 = (uint32_t)__cvta_generic_to_shared(&h1b[pr * 128 + ubase + pu]);
    const uint32_t h1a1 = h1a0 + HB * 4;
    const uint32_t h2a0 = (uint32_t)__cvta_generic_to_shared(&h2b[pr * 128 + ubase + pu]);
    const uint32_t h2a1 = h2a0 + HB * 4;

    // rows this thread stores after shfl-reduce
    const int rst = (lane >> 3) * 2;

    // ================= Prologue: gemmA(0) + h1(0) -> h1b buf1 ==============
    {
        unsigned long long accA[8] = {0,0,0,0,0,0,0,0};
        seg_acc(w0, h1b, col, kb, accA);
        float red[8];
#pragma unroll
        for (int r = 0; r < 8; r++) {
            float v = hsum2(accA[r]);
            v += __shfl_xor_sync(0xffffffffu, v, 8);
            v += __shfl_xor_sync(0xffffffffu, v, 16);
            red[r] = v;
        }
        gsA[(rst + 0) * 128 + col] = red[rst + 0];
        gsA[(rst + 1) * 128 + col] = red[rst + 1];
        __syncthreads();

        if (tid < 256) {
            const float* xp = &g_xpre[((size_t)(brow0 + pr)) * GC + ubase + pu];
            float gi = gsA[pr * 128 +       pu] + __ldg(&xp[0 * H]);
            float gf = gsA[pr * 128 +  32 + pu] + __ldg(&xp[1 * H]);
            float gg = gsA[pr * 128 +  64 + pu] + __ldg(&xp[2 * H]);
            float go = gsA[pr * 128 +  96 + pu] + __ldg(&xp[3 * H]);
            float iv = sigm(gi), fv = sigm(gf), gv = tanhx(gg), ov = sigm(go);
            c1 = fv * c1 + iv * gv;
            float h1v = ov * tanhx(c1);
#pragma unroll
            for (int rk = 0; rk < 4; rk++) st_peer_f32(h1a1, rk, h1v);  // buf1
        }
        cluster_sync_();
    }

    // ============ Main loop: iteration i computes h2(i) and h1(i+1) ========
    for (int i = 0; i < T_STEPS; i++) {
        const int p = i & 1;
        const float* h1cur = h1b + (p ^ 1) * HB;   // h1[i]
        const float* h2cur = h2b + p * HB;         // h2[i-1]

        // prefetch xpre[i+1] for layer-0 pointwise (hidden behind gemm burst)
        float xg0 = 0.f, xg1 = 0.f, xg2 = 0.f, xg3 = 0.f;
        if (tid < 256 && i < T_STEPS - 1) {
            const float* xp = &g_xpre[((size_t)(i + 1) * BATCH + brow0 + pr) * GC + ubase + pu];
            xg0 = __ldg(&xp[0 * H]);
            xg1 = __ldg(&xp[1 * H]);
            xg2 = __ldg(&xp[2 * H]);
            xg3 = __ldg(&xp[3 * H]);
        }

        // -------- merged GEMM burst: A(i+1) and B(i) --------
        unsigned long long accA[8] = {0,0,0,0,0,0,0,0};
        unsigned long long accB[8] = {0,0,0,0,0,0,0,0};
        seg_acc(w0,  h1cur, col, kb, accA);   // W_hh0 . h1[i]   -> gates0(i+1)
        seg_acc(w1i, h1cur, col, kb, accB);   // W_ih1 . h1[i]   -> gates1(i)
        seg_acc(w1h, h2cur, col, kb, accB);   // W_hh1 . h2[i-1] -> gates1(i)

        float redA[8], redB[8];
#pragma unroll
        for (int r = 0; r < 8; r++) {
            float va = hsum2(accA[r]);
            va += __shfl_xor_sync(0xffffffffu, va, 8);
            va += __shfl_xor_sync(0xffffffffu, va, 16);
            redA[r] = va;
            float vb = hsum2(accB[r]);
            vb += __shfl_xor_sync(0xffffffffu, vb, 8);
            vb += __shfl_xor_sync(0xffffffffu, vb, 16);
            redB[r] = vb;
        }
        gsA[(rst + 0) * 128 + col] = redA[rst + 0];
        gsA[(rst + 1) * 128 + col] = redA[rst + 1];
        gsB[(rst + 0) * 128 + col] = redB[rst + 0];
        gsB[(rst + 1) * 128 + col] = redB[rst + 1];
        __syncthreads();

        // -------- split pointwise --------
        if (tid < 256) {
            if (i < T_STEPS - 1) {     // layer-0 pointwise for step i+1
                float gi = gsA[pr * 128 +       pu] + xg0;
                float gf = gsA[pr * 128 +  32 + pu] + xg1;
                float gg = gsA[pr * 128 +  64 + pu] + xg2;
                float go = gsA[pr * 128 +  96 + pu] + xg3;
                float iv = sigm(gi), fv = sigm(gf), gv = tanhx(gg), ov = sigm(go);
                c1 = fv * c1 + iv * gv;
                float h1v = ov * tanhx(c1);
                uint32_t a = p ? h1a1 : h1a0;      // write buf (i&1)
#pragma unroll
                for (int rk = 0; rk < 4; rk++) st_peer_f32(a, rk, h1v);
            }
        } else {                       // layer-1 pointwise for step i
            float gi = gsB[pr * 128 +       pu] + bb0;
            float gf = gsB[pr * 128 +  32 + pu] + bb1;
            float gg = gsB[pr * 128 +  64 + pu] + bb2;
            float go = gsB[pr * 128 +  96 + pu] + bb3;
            float iv = sigm(gi), fv = sigm(gf), gv = tanhx(gg), ov = sigm(go);
            c2 = fv * c2 + iv * gv;
            float h2v = ov * tanhx(c2);
            uint32_t a = p ? h2a0 : h2a1;          // write buf ((i+1)&1)
#pragma unroll
            for (int rk = 0; rk < 4; rk++) st_peer_f32(a, rk, h2v);
            if (i == T_STEPS - 1)
                out[(size_t)(brow0 + pr) * H + ubase + pu] = h2v;
        }
        cluster_sync_();   // publishes h1[i+1] and h2[i] cluster-wide
    }
}

// ---------------------------------------------------------------
extern "C" void kernel_launch(void* const* d_in, const int* in_sizes, int n_in,
                              void* d_out, int out_size)
{
    const float* x    = (const float*)d_in[0];
    const float* h0   = (const float*)d_in[1];
    const float* c0   = (const float*)d_in[2];
    const float* Wih0 = (const float*)d_in[3];
    const float* Whh0 = (const float*)d_in[4];
    const float* bih0 = (const float*)d_in[5];
    const float* bhh0 = (const float*)d_in[6];
    const float* Wih1 = (const float*)d_in[7];
    const float* Whh1 = (const float*)d_in[8];
    const float* bih1 = (const float*)d_in[9];
    const float* bhh1 = (const float*)d_in[10];
    float* out = (float*)d_out;

    cudaFuncSetAttribute(precompute_kernel,
                         cudaFuncAttributeMaxDynamicSharedMemorySize, PRE_SMEM);
    cudaFuncSetAttribute(lstm_recurrent_kernel,
                         cudaFuncAttributeMaxDynamicSharedMemorySize, REC_SMEM);

    dim3 pgrid(T_STEPS, 4, 8);
    precompute_kernel<<<pgrid, 256, PRE_SMEM>>>(x, Wih0, bih0, bhh0);

    lstm_recurrent_kernel<<<TEAMS * 4, 512, REC_SMEM>>>(
        h0, c0, Whh0, Wih1, Whh1, bih1, bhh1, out);
}

// round 12
// speedup vs baseline: 2.0246x; 1.4199x over previous
#include <cuda_runtime.h>
#include <cstdint>
#include <cstddef>

// Problem dims
#define T_STEPS 512
#define BATCH   256
#define NF      160
#define H       128
#define GC      512   // 4*H gate columns

// Recurrent org: 32 clusters x 4 CTAs x 384 threads (12 warps).
// Team owns 8 batch rows; CTA owns 32 hidden units (=128 gate cols) of BOTH layers.
// Register-blocked merged GEMM: A-warps (0-3) do W_hh0, B-warps (4-11) do
// W_ih1+W_hh1 folded. Weights read from smem exactly once per iteration.
#define TEAMS 32
#define ROWS_PER_TEAM 8
#define UNITS_PER_CTA 32
#define HB 1024   // floats per h buffer (8 rows x 128)

// -------- global scratch (static __device__, allocation-free) --------
__device__ float g_xpre[(size_t)T_STEPS * BATCH * GC];       // 256 MB

// ---------------- f32x2 helpers ----------------
__device__ __forceinline__ void ffma2(unsigned long long& d,
                                      unsigned long long a,
                                      unsigned long long b) {
    asm("fma.rn.f32x2 %0, %1, %2, %0;" : "+l"(d) : "l"(a), "l"(b));
}
__device__ __forceinline__ float hsum2(unsigned long long v) {
    unsigned lo, hi;
    asm("mov.b64 {%0,%1}, %2;" : "=r"(lo), "=r"(hi) : "l"(v));
    return __uint_as_float(lo) + __uint_as_float(hi);
}

// ---------------- cluster helpers ----------------
__device__ __forceinline__ void cluster_sync_() {
    asm volatile("barrier.cluster.arrive.aligned;" ::: "memory");
    asm volatile("barrier.cluster.wait.aligned;" ::: "memory");
}
__device__ __forceinline__ unsigned ctarank_() {
    unsigned r;
    asm("mov.u32 %0, %%cluster_ctarank;" : "=r"(r));
    return r;
}
__device__ __forceinline__ void st_peer_f32(uint32_t local_smem_addr, int rank, float v) {
    uint32_t ra;
    asm("mapa.shared::cluster.u32 %0, %1, %2;" : "=r"(ra) : "r"(local_smem_addr), "r"(rank));
    asm volatile("st.shared::cluster.f32 [%0], %1;" :: "r"(ra), "f"(v) : "memory");
}

// Swizzled weight layout: col row = 128 floats = 32 chunks of 16B.
// word offset of (col,k):  col*128 + ((k>>2)^(col&7))*4  -> conflict-free
__device__ __forceinline__ int wswz(int col, int k) {
    return col * 128 + (((k >> 2) ^ (col & 7)) << 2);
}

// ---------------------------------------------------------------
// Precompute kernel (unchanged, known-good)
#define PRE_SMEM (2 * 64 * 164 * 4)
__global__ __launch_bounds__(256) void precompute_kernel(
    const float* __restrict__ x,
    const float* __restrict__ Wih0,
    const float* __restrict__ bih0,
    const float* __restrict__ bhh0)
{
    extern __shared__ float sm[];
    float* xs = sm;              // [64][164]
    float* ws = sm + 64 * 164;   // [64][164]

    const int t   = blockIdx.x;
    const int b0  = blockIdx.y * 64;
    const int gc0 = blockIdx.z * 64;
    const int tid = threadIdx.x;

    for (int idx = tid; idx < 64 * 40; idx += 256) {
        int row = idx / 40;
        int q   = (idx % 40) * 4;
        *(float4*)&xs[row * 164 + q] =
            *(const float4*)&x[((size_t)(b0 + row) * T_STEPS + t) * NF + q];
        *(float4*)&ws[row * 164 + q] =
            *(const float4*)&Wih0[(size_t)(gc0 + row) * NF + q];
    }
    __syncthreads();

    const int tx = tid & 15;
    const int ty = tid >> 4;

    unsigned long long acc[4][4];
#pragma unroll
    for (int i = 0; i < 4; i++)
#pragma unroll
        for (int j = 0; j < 4; j++) acc[i][j] = 0ull;

#pragma unroll 4
    for (int k = 0; k < NF; k += 4) {
        ulonglong2 av[4], bv[4];
#pragma unroll
        for (int i = 0; i < 4; i++) av[i] = *(const ulonglong2*)&xs[(ty + 16 * i) * 164 + k];
#pragma unroll
        for (int j = 0; j < 4; j++) bv[j] = *(const ulonglong2*)&ws[(tx + 16 * j) * 164 + k];
#pragma unroll
        for (int i = 0; i < 4; i++)
#pragma unroll
            for (int j = 0; j < 4; j++) {
                ffma2(acc[i][j], av[i].x, bv[j].x);
                ffma2(acc[i][j], av[i].y, bv[j].y);
            }
    }

#pragma unroll
    for (int i = 0; i < 4; i++) {
        int b = b0 + ty + 16 * i;
#pragma unroll
        for (int j = 0; j < 4; j++) {
            int gc = gc0 + tx + 16 * j;
            float bias = __ldg(&bih0[gc]) + __ldg(&bhh0[gc]);
            g_xpre[((size_t)t * BATCH + b) * GC + gc] = hsum2(acc[i][j]) + bias;
        }
    }
}

// ---------------------------------------------------------------
__device__ __forceinline__ float sigm(float v)  { return 1.0f / (1.0f + __expf(-v)); }
__device__ __forceinline__ float tanhx(float v) { return 1.0f - 2.0f / (__expf(2.0f * v) + 1.0f); }

// smem: 3 swizzled weight slices (64KB ea) + 2x2 h buffers + shared gs + bias
// = 196608 + 16384 + 16384 + 512 = 229888 B  (< 232448 limit)
#define REC_SMEM ((3 * 128 * 128 + 2 * HB + 2 * HB + 4 * 1024 + 128) * 4)

__global__ __launch_bounds__(384, 1) __cluster_dims__(4, 1, 1)
void lstm_recurrent_kernel(
    const float* __restrict__ h0,
    const float* __restrict__ c0,
    const float* __restrict__ Whh0,
    const float* __restrict__ Wih1,
    const float* __restrict__ Whh1,
    const float* __restrict__ bih1,
    const float* __restrict__ bhh1,
    float* __restrict__ out)
{
    extern __shared__ float sm[];
    float* w0  = sm;                   // [128 cols][128] swizzled W_hh0 slice
    float* w1i = w0  + 128 * 128;
    float* w1h = w1i + 128 * 128;
    float* h1b = w1h + 128 * 128;      // [2][8][128]
    float* h2b = h1b + 2 * HB;         // [2][8][128]
    float* gs  = h2b + 2 * HB;         // [4 kp][8][128] shared staging (A then B)
    float* b1s = gs  + 4 * 1024;       // [128]

    const int tid   = threadIdx.x;
    const int team  = blockIdx.x >> 2;
    const int rank  = (int)ctarank_();
    const int brow0 = team * ROWS_PER_TEAM;
    const int ubase = rank * UNITS_PER_CTA;

    // --- load weight slices into swizzled smem (local col j = gate*32+unit) ---
    for (int idx = tid; idx < 128 * 32; idx += 384) {
        int j = idx >> 5;           // local col
        int q = idx & 31;           // 16B chunk
        int grow = (j >> 5) * H + ubase + (j & 31);
        int dst = j * 128 + ((q ^ (j & 7)) << 2);
        *(float4*)&w0 [dst] = *(const float4*)&Whh0[(size_t)grow * H + q * 4];
        *(float4*)&w1i[dst] = *(const float4*)&Wih1[(size_t)grow * H + q * 4];
        *(float4*)&w1h[dst] = *(const float4*)&Whh1[(size_t)grow * H + q * 4];
    }
    for (int j = tid; j < 128; j += 384) {
        int grow = (j >> 5) * H + ubase + (j & 31);
        b1s[j] = bih1[grow] + bhh1[grow];
    }
    // initial h: h1[-1] -> h1b buf0, h2[-1] -> h2b buf0
    for (int idx = tid; idx < 8 * 32; idx += 384) {
        int r = idx >> 5;
        int q = (idx & 31) * 4;
        *(float4*)&h1b[r * 128 + q] = *(const float4*)&h0[((size_t)(brow0 + r)) * H + q];
        *(float4*)&h2b[r * 128 + q] = *(const float4*)&h0[((size_t)(BATCH + brow0 + r)) * H + q];
    }
    __syncthreads();

    // pointwise mapping (threads 0-255 do BOTH layers' pointwise)
    const int pr = (tid >> 5) & 7;
    const int pu = tid & 31;
    float c1 = 0.f, c2 = 0.f, bb0 = 0.f, bb1 = 0.f, bb2 = 0.f, bb3 = 0.f;
    if (tid < 256) {
        c1 = c0[((size_t)(brow0 + pr)) * H + ubase + pu];
        c2 = c0[((size_t)(BATCH + brow0 + pr)) * H + ubase + pu];
        bb0 = b1s[      pu];
        bb1 = b1s[ 32 + pu];
        bb2 = b1s[ 64 + pu];
        bb3 = b1s[ 96 + pu];
    }
    cluster_sync_();

    // GEMM warp roles
    const int warp = tid >> 5;
    const int lane = tid & 31;
    const bool isA = (warp < 4);
    // A: kp = warp, unit = lane, cols = {unit+32j}
    const int kbA = warp * 32;
    // B: w4 = warp-4: kp = w4>>1, cg = (w4&1)*32 + lane, cols = {cg, cg+64}
    const int w4  = warp - 4;
    const int kbB = (w4 >> 1) * 32;
    const int cgB = ((w4 & 1) << 5) + lane;

    // per-buffer smem addresses of this thread's pointwise h element
    const uint32_t h1a0 = (uint32_t)__cvta_generic_to_shared(&h1b[pr * 128 + ubase + pu]);
    const uint32_t h1a1 = h1a0 + HB * 4;
    const uint32_t h2a0 = (uint32_t)__cvta_generic_to_shared(&h2b[pr * 128 + ubase + pu]);
    const uint32_t h2a1 = h2a0 + HB * 4;

    // ---------------- Prologue: gemmA(0) + h1(0) -> h1b buf1 ----------------
    {
        if (isA) {
            unsigned long long acc[4][8];
#pragma unroll
            for (int j = 0; j < 4; j++)
#pragma unroll
                for (int r = 0; r < 8; r++) acc[j][r] = 0ull;
#pragma unroll
            for (int ch = 0; ch < 8; ch++) {
                int k = kbA + ch * 4;
                ulonglong2 hv[8];
#pragma unroll
                for (int r = 0; r < 8; r++) hv[r] = *(const ulonglong2*)&h1b[r * 128 + k];
#pragma unroll
                for (int j = 0; j < 4; j++) {
                    ulonglong2 wv = *(const ulonglong2*)&w0[wswz(lane + 32 * j, k)];
#pragma unroll
                    for (int r = 0; r < 8; r++) {
                        ffma2(acc[j][r], wv.x, hv[r].x);
                        ffma2(acc[j][r], wv.y, hv[r].y);
                    }
                }
            }
#pragma unroll
            for (int j = 0; j < 4; j++)
#pragma unroll
                for (int r = 0; r < 8; r++)
                    gs[warp * 1024 + r * 128 + 32 * j + lane] = hsum2(acc[j][r]);
        }
        __syncthreads();
        if (tid < 256) {
            const float* xp = &g_xpre[((size_t)(brow0 + pr)) * GC + ubase + pu];
            float gi = __ldg(&xp[0 * H]);
            float gf = __ldg(&xp[1 * H]);
            float gg = __ldg(&xp[2 * H]);
            float go = __ldg(&xp[3 * H]);
#pragma unroll
            for (int q = 0; q < 4; q++) {
                const float* gq = &gs[q * 1024 + pr * 128];
                gi += gq[      pu];
                gf += gq[ 32 + pu];
                gg += gq[ 64 + pu];
                go += gq[ 96 + pu];
            }
            float iv = sigm(gi), fv = sigm(gf), gv = tanhx(gg), ov = sigm(go);
            c1 = fv * c1 + iv * gv;
            float h1v = ov * tanhx(c1);
#pragma unroll
            for (int rk = 0; rk < 4; rk++) st_peer_f32(h1a1, rk, h1v);  // buf1
        }
        cluster_sync_();
    }

    // ---------- Main loop: iteration i computes h2(i) and h1(i+1) ----------
    for (int i = 0; i < T_STEPS; i++) {
        const int p = i & 1;
        const float* h1cur = h1b + (p ^ 1) * HB;   // h1[i]
        const float* h2cur = h2b + p * HB;         // h2[i-1]

        // prefetch xpre[i+1] (hidden behind GEMM burst)
        float xg0 = 0.f, xg1 = 0.f, xg2 = 0.f, xg3 = 0.f;
        if (tid < 256 && i < T_STEPS - 1) {
            const float* xp = &g_xpre[((size_t)(i + 1) * BATCH + brow0 + pr) * GC + ubase + pu];
            xg0 = __ldg(&xp[0 * H]);
            xg1 = __ldg(&xp[1 * H]);
            xg2 = __ldg(&xp[2 * H]);
            xg3 = __ldg(&xp[3 * H]);
        }

        unsigned long long accB[2][8];
        if (isA) {
            // ---- gemmA: W_hh0 . h1[i], 4 cols x 8 rows x 32k ----
            unsigned long long acc[4][8];
#pragma unroll
            for (int j = 0; j < 4; j++)
#pragma unroll
                for (int r = 0; r < 8; r++) acc[j][r] = 0ull;
#pragma unroll
            for (int ch = 0; ch < 8; ch++) {
                int k = kbA + ch * 4;
                ulonglong2 hv[8];
#pragma unroll
                for (int r = 0; r < 8; r++) hv[r] = *(const ulonglong2*)&h1cur[r * 128 + k];
#pragma unroll
                for (int j = 0; j < 4; j++) {
                    ulonglong2 wv = *(const ulonglong2*)&w0[wswz(lane + 32 * j, k)];
#pragma unroll
                    for (int r = 0; r < 8; r++) {
                        ffma2(acc[j][r], wv.x, hv[r].x);
                        ffma2(acc[j][r], wv.y, hv[r].y);
                    }
                }
            }
            // store A partials into gs
#pragma unroll
            for (int j = 0; j < 4; j++)
#pragma unroll
                for (int r = 0; r < 8; r++)
                    gs[warp * 1024 + r * 128 + 32 * j + lane] = hsum2(acc[j][r]);
        } else {
            // ---- gemmB: W_ih1 . h1[i] + W_hh1 . h2[i-1], 2 cols x 8 rows, folded K ----
#pragma unroll
            for (int j = 0; j < 2; j++)
#pragma unroll
                for (int r = 0; r < 8; r++) accB[j][r] = 0ull;
#pragma unroll
            for (int ch = 0; ch < 8; ch++) {
                int k = kbB + ch * 4;
                ulonglong2 hv[8];
#pragma unroll
                for (int r = 0; r < 8; r++) hv[r] = *(const ulonglong2*)&h1cur[r * 128 + k];
#pragma unroll
                for (int j = 0; j < 2; j++) {
                    ulonglong2 wv = *(const ulonglong2*)&w1i[wswz(cgB + 64 * j, k)];
#pragma unroll
                    for (int r = 0; r < 8; r++) {
                        ffma2(accB[j][r], wv.x, hv[r].x);
                        ffma2(accB[j][r], wv.y, hv[r].y);
                    }
                }
            }
#pragma unroll
            for (int ch = 0; ch < 8; ch++) {
                int k = kbB + ch * 4;
                ulonglong2 hv[8];
#pragma unroll
                for (int r = 0; r < 8; r++) hv[r] = *(const ulonglong2*)&h2cur[r * 128 + k];
#pragma unroll
                for (int j = 0; j < 2; j++) {
                    ulonglong2 wv = *(const ulonglong2*)&w1h[wswz(cgB + 64 * j, k)];
#pragma unroll
                    for (int r = 0; r < 8; r++) {
                        ffma2(accB[j][r], wv.x, hv[r].x);
                        ffma2(accB[j][r], wv.y, hv[r].y);
                    }
                }
            }
        }
        __syncthreads();   // A partials visible; B still holds accB in regs

        // ---- pointwise layer-0 -> h1[i+1] ----
        if (tid < 256 && i < T_STEPS - 1) {
            float gi = xg0, gf = xg1, gg = xg2, go = xg3;
#pragma unroll
            for (int q = 0; q < 4; q++) {
                const float* gq = &gs[q * 1024 + pr * 128];
                gi += gq[      pu];
                gf += gq[ 32 + pu];
                gg += gq[ 64 + pu];
                go += gq[ 96 + pu];
            }
            float iv = sigm(gi), fv = sigm(gf), gv = tanhx(gg), ov = sigm(go);
            c1 = fv * c1 + iv * gv;
            float h1v = ov * tanhx(c1);
            uint32_t a = p ? h1a1 : h1a0;
#pragma unroll
            for (int rk = 0; rk < 4; rk++) st_peer_f32(a, rk, h1v);
        }
        __syncthreads();   // gs reads done; B may overwrite

        if (!isA) {
#pragma unroll
            for (int j = 0; j < 2; j++)
#pragma unroll
                for (int r = 0; r < 8; r++)
                    gs[kbB * 32 + r * 128 + cgB + 64 * j] = hsum2(accB[j][r]);
        }
        __syncthreads();   // B partials visible

        // ---- pointwise layer-1 -> h2[i] ----
        if (tid < 256) {
            float gi = bb0, gf = bb1, gg = bb2, go = bb3;
#pragma unroll
            for (int q = 0; q < 4; q++) {
                const float* gq = &gs[q * 1024 + pr * 128];
                gi += gq[      pu];
                gf += gq[ 32 + pu];
                gg += gq[ 64 + pu];
                go += gq[ 96 + pu];
            }
            float iv = sigm(gi), fv = sigm(gf), gv = tanhx(gg), ov = sigm(go);
            c2 = fv * c2 + iv * gv;
            float h2v = ov * tanhx(c2);
            uint32_t a = p ? h2a0 : h2a1;
#pragma unroll
            for (int rk = 0; rk < 4; rk++) st_peer_f32(a, rk, h2v);
            if (i == T_STEPS - 1)
                out[(size_t)(brow0 + pr) * H + ubase + pu] = h2v;
        }
        cluster_sync_();   // publishes h1[i+1] and h2[i]; orders gs for next iter
    }
}

// ---------------------------------------------------------------
extern "C" void kernel_launch(void* const* d_in, const int* in_sizes, int n_in,
                              void* d_out, int out_size)
{
    const float* x    = (const float*)d_in[0];
    const float* h0   = (const float*)d_in[1];
    const float* c0   = (const float*)d_in[2];
    const float* Wih0 = (const float*)d_in[3];
    const float* Whh0 = (const float*)d_in[4];
    const float* bih0 = (const float*)d_in[5];
    const float* bhh0 = (const float*)d_in[6];
    const float* Wih1 = (const float*)d_in[7];
    const float* Whh1 = (const float*)d_in[8];
    const float* bih1 = (const float*)d_in[9];
    const float* bhh1 = (const float*)d_in[10];
    float* out = (float*)d_out;

    cudaFuncSetAttribute(precompute_kernel,
                         cudaFuncAttributeMaxDynamicSharedMemorySize, PRE_SMEM);
    cudaFuncSetAttribute(lstm_recurrent_kernel,
                         cudaFuncAttributeMaxDynamicSharedMemorySize, REC_SMEM);

    dim3 pgrid(T_STEPS, 4, 8);
    precompute_kernel<<<pgrid, 256, PRE_SMEM>>>(x, Wih0, bih0, bhh0);

    lstm_recurrent_kernel<<<TEAMS * 4, 384, REC_SMEM>>>(
        h0, c0, Whh0, Wih1, Whh1, bih1, bhh1, out);
}